// round 8
// baseline (speedup 1.0000x reference)
#include <cuda_runtime.h>
#include <math.h>

#define BB 4
#define LL 512
#define VV 32128
#define AVV 32000
#define DD 768
#define NT (BB*LL)
#define NV4 (VV/4)      // 8032
#define ND4 (DD/4)      // 192
#define NTH 256
#define CH 4            // chunks per token
#define CV4 (NV4/CH)    // 2008 float4 per chunk
#define NW  (NTH/32)    // 8 warps
#define PPT (CH*NW)     // 32 partials per token

// Scratch (device globals; no allocation allowed)
__device__ int4 g_part[NT * PPT];  // per (token, chunk, warp) top-2
__device__ int2 g_idx[NT];         // {embed row or -1, psg row or -1}

// ---------------------------------------------------------------------------
// Exact coarse key: lo - log(-log u). Series path near u=1: winners have
// u ~ 1-3e-5 where __logf's ~1e-6 ABSOLUTE error would be catastrophic
// relative error on t = -log u. Abs key error bounded ~1.2e-4.
// ---------------------------------------------------------------------------
__device__ __forceinline__ float coarse_key(float lo, float u) {
    float w  = 1.0f - u;                 // exact for u > 0.5 (Sterbenz)
    float ts = fmaf(0.5f * w, w, w);     // w + w^2/2
    float tl = -__logf(u);
    float t  = (u > 0.99609375f) ? ts : tl;
    return lo - __logf(t);
}

__device__ __forceinline__ double precise_key(float lo, float u) {
    return (double)lo - log(-log((double)u));
}

__device__ __forceinline__ void ins2(float k, int j,
                                     float& v1, int& i1,
                                     float& v2, int& i2) {
    bool p = k > v1;
    float dv = p ? v1 : k;
    int   di = p ? i1 : j;
    if (p) { v1 = k; i1 = j; }
    if (dv > v2) { v2 = dv; i2 = di; }
}

__device__ __forceinline__ void top2_insert(float w, int j,
                                            float& v1, int& i1,
                                            float& v2, int& i2) {
    if (w > v1 || (w == v1 && j < i1)) {
        v2 = v1; i2 = i1; v1 = w; i1 = j;
    } else if (w > v2 || (w == v2 && j < i2)) {
        v2 = w; i2 = j;
    }
}

// ---------------------------------------------------------------------------
// K0: psg prep. One warp per batch, shuffle reductions only.
// ---------------------------------------------------------------------------
__global__ void __launch_bounds__(32)
psg_prep_kernel(const int* __restrict__ rwrt,
                const int* __restrict__ psg_in) {
    __shared__ int s_r[LL];
    __shared__ int s_p[LL];
    const int b    = blockIdx.x;
    const int lane = threadIdx.x;

    int cnt = 0;
#pragma unroll
    for (int k = 0; k < LL / 32; k++) {
        int l  = lane + 32 * k;
        int rv = rwrt[b * LL + l];
        s_r[l] = rv;
        s_p[l] = psg_in[b * LL + l];
        cnt += (rv == 1);
    }
    __syncwarp();
#pragma unroll
    for (int o = 16; o > 0; o >>= 1) cnt += __shfl_xor_sync(0xFFFFFFFFu, cnt, o);
    const int shift = cnt;

    int tr[LL / 32];
    int firstnz = LL;
#pragma unroll
    for (int k = 0; k < LL / 32; k++) {
        int l   = lane + 32 * k;
        int pos = ((l - shift) % LL + LL) % LL;
        int fm  = 1 - s_r[LL - 1 - pos];
        int psv = (pos == 0) ? 1 : s_p[pos - 1];
        int t   = fm * psv;
        tr[k] = t;
        if (t != 0) firstnz = min(firstnz, l);
    }
#pragma unroll
    for (int o = 16; o > 0; o >>= 1)
        firstnz = min(firstnz, __shfl_xor_sync(0xFFFFFFFFu, firstnz, o));

#pragma unroll
    for (int k = 0; k < LL / 32; k++) {
        int l = lane + 32 * k;
        // psg id (embed id filled by decide_kernel)
        g_idx[b * LL + l].y = (l >= firstnz) ? tr[k] : -1;
    }
}

// ---------------------------------------------------------------------------
// K1: streaming scan. Per-element bit-log UB filter (best measured);
// warp-level reductions only (single __syncthreads for seed-thr share).
// ---------------------------------------------------------------------------
__global__ void __launch_bounds__(NTH)
scan_kernel(const float* __restrict__ logits,
            const float* __restrict__ gu) {
    const int blk  = blockIdx.x;
    const int t    = blk >> 2;
    const int c    = blk & 3;
    const int tid  = threadIdx.x;
    const int wid  = tid >> 5;
    const int lane = tid & 31;

    const float4* lg = (const float4*)(logits + (size_t)t * VV) + c * CV4;
    const float4* gg = (const float4*)(gu     + (size_t)t * VV) + c * CV4;
    const int jbase = c * CV4 * 4;

    float v1 = -INFINITY, v2 = -INFINITY;
    int   i1 = 0,         i2 = 1;

    // ---- seed: one exact float4 per thread ----
    {
        float4 a = __ldcs(lg + tid);
        float4 g = __ldcs(gg + tid);
        int base = jbase + 4 * tid;
        ins2(coarse_key(a.x, g.x), base + 0, v1, i1, v2, i2);
        ins2(coarse_key(a.y, g.y), base + 1, v1, i1, v2, i2);
        ins2(coarse_key(a.z, g.z), base + 2, v1, i1, v2, i2);
        ins2(coarse_key(a.w, g.w), base + 3, v1, i1, v2, i2);
    }
    // warp 2nd-max of seed keys (<= global #2, provable: 2nd of subset <= 2nd of set)
    float sa = v1, sb = v2;
#pragma unroll
    for (int off = 16; off > 0; off >>= 1) {
        float oa = __shfl_xor_sync(0xFFFFFFFFu, sa, off);
        float ob = __shfl_xor_sync(0xFFFFFFFFu, sb, off);
        float hi  = fmaxf(sa, oa);
        float lo2 = fmaxf(fminf(sa, oa), fmaxf(sb, ob));
        sa = hi; sb = lo2;
    }
    // share across warps: thr = max_w (warp 2nd-max)  -- ONE barrier total
    __shared__ float s_sb[NW];
    if (lane == 0) s_sb[wid] = sb;
    __syncthreads();
    float thr = sb;
#pragma unroll
    for (int wv = 0; wv < NW; wv++) thr = fmaxf(thr, s_sb[wv]);
    thr = fmaxf(thr, v2);

    // ---- main loop: per-element independent bit-log UB filter ----
    const float CB  = 88.029693f;       // 127 * ln2
    const float CC  = 8.2629582e-8f;    // ln2 / 2^23
    const float EPS = 1e-5f;            // I2F rounding margin

    for (int i = tid + NTH; i < CV4; i += NTH) {
        float4 a = __ldcs(lg + i);
        float4 g = __ldcs(gg + i);
        // one-sided: key <= lo - ln2*l2a(1-u)  since -log u >= 1-u, l2a <= log2
        float ub0 = fmaf(-CC, (float)__float_as_int(1.0f - g.x), a.x + CB + EPS);
        float ub1 = fmaf(-CC, (float)__float_as_int(1.0f - g.y), a.y + CB + EPS);
        float ub2 = fmaf(-CC, (float)__float_as_int(1.0f - g.z), a.z + CB + EPS);
        float ub3 = fmaf(-CC, (float)__float_as_int(1.0f - g.w), a.w + CB + EPS);
        if (ub0 > thr || ub1 > thr || ub2 > thr || ub3 > thr) {
            int base = jbase + 4 * i;
            ins2(coarse_key(a.x, g.x), base + 0, v1, i1, v2, i2);
            ins2(coarse_key(a.y, g.y), base + 1, v1, i1, v2, i2);
            ins2(coarse_key(a.z, g.z), base + 2, v1, i1, v2, i2);
            ins2(coarse_key(a.w, g.w), base + 3, v1, i1, v2, i2);
            thr = fmaxf(thr, v2);
        }
    }

    // ---- warp top-2 reduction (shuffle only, index tie-break) ----
#pragma unroll
    for (int off = 16; off > 0; off >>= 1) {
        float w1 = __shfl_xor_sync(0xFFFFFFFFu, v1, off);
        int   j1 = __shfl_xor_sync(0xFFFFFFFFu, i1, off);
        float w2 = __shfl_xor_sync(0xFFFFFFFFu, v2, off);
        int   j2 = __shfl_xor_sync(0xFFFFFFFFu, i2, off);
        top2_insert(w1, j1, v1, i1, v2, i2);
        top2_insert(w2, j2, v1, i1, v2, i2);
    }
    if (lane == 0) {
        g_part[t * PPT + c * NW + wid] =
            make_int4(__float_as_int(v1), i1, __float_as_int(v2), i2);
    }
}

// ---------------------------------------------------------------------------
// K2: decide. 8 blocks x 256, one thread per token: merge 32 partials
// (512B contiguous), fp64 near-tie recheck, fold rwrt/AV mask.
// ---------------------------------------------------------------------------
__global__ void __launch_bounds__(NTH)
decide_kernel(const float* __restrict__ logits,
              const float* __restrict__ gu,
              const int*   __restrict__ rwrt) {
    const int t = blockIdx.x * NTH + threadIdx.x;   // 0..NT-1

    float v1 = -INFINITY, v2 = -INFINITY;
    int   i1 = 0,         i2 = 1;
#pragma unroll
    for (int cc = 0; cc < PPT; cc++) {
        int4 pr = g_part[t * PPT + cc];
        top2_insert(__int_as_float(pr.x), pr.y, v1, i1, v2, i2);
        top2_insert(__int_as_float(pr.z), pr.w, v1, i1, v2, i2);
    }
    int win = i1;
    if (v1 - v2 < 0.02f) {
        double k1 = precise_key(logits[(size_t)t * VV + i1],
                                gu[(size_t)t * VV + i1]);
        double k2 = precise_key(logits[(size_t)t * VV + i2],
                                gu[(size_t)t * VV + i2]);
        if (k2 > k1 || (k2 == k1 && i2 < i1)) win = i2;
    }
    g_idx[t].x = (rwrt[t] != 0 && win < AVV) ? win : -1;
}

// ---------------------------------------------------------------------------
// K3: pure gather. One float4 per thread, no smem, no barriers. 1536 blocks.
// ---------------------------------------------------------------------------
__global__ void __launch_bounds__(NTH)
gather_kernel(const float* __restrict__ W,
              float*       __restrict__ out) {
    const int idx = blockIdx.x * NTH + threadIdx.x;   // 0 .. NT*ND4-1
    const int t   = idx / ND4;
    const int d   = idx - t * ND4;

    const float4* W4 = (const float4*)W;
    int2 id = *(const int2*)&g_idx[t];

    float4 acc = make_float4(0.f, 0.f, 0.f, 0.f);
    if (id.x >= 0) acc = W4[(size_t)id.x * ND4 + d];
    if (id.y >= 0) {
        float4 wv = W4[(size_t)id.y * ND4 + d];
        acc.x += wv.x; acc.y += wv.y; acc.z += wv.z; acc.w += wv.w;
    }
    ((float4*)out)[idx] = acc;
}

// ---------------------------------------------------------------------------
extern "C" void kernel_launch(void* const* d_in, const int* in_sizes, int n_in,
                              void* d_out, int out_size) {
    const float* logits = (const float*)d_in[0];
    const float* gu     = (const float*)d_in[1];
    const float* W      = (const float*)d_in[2];
    const int*   rwrt   = (const int*)d_in[3];
    const int*   psg    = (const int*)d_in[4];
    float* out = (float*)d_out;

    psg_prep_kernel<<<BB, 32>>>(rwrt, psg);
    scan_kernel<<<NT * CH, NTH>>>(logits, gu);
    decide_kernel<<<NT / NTH, NTH>>>(logits, gu, rwrt);
    gather_kernel<<<(NT * ND4) / NTH, NTH>>>(W, out);
}

// round 9
// speedup vs baseline: 1.0143x; 1.0143x over previous
#include <cuda_runtime.h>
#include <math.h>

#define BB 4
#define LL 512
#define VV 32128
#define AVV 32000
#define DD 768
#define NT (BB*LL)
#define NV4 (VV/4)      // 8032
#define ND4 (DD/4)      // 192
#define NTH 256
#define CH 4            // chunks per token
#define CV4 (NV4/CH)    // 2008 float4 per chunk

// Scratch (device globals; no allocation allowed)
__device__ int4 g_part[NT * CH];   // per (token,chunk) top-2: {bits(v1),i1,bits(v2),i2}
__device__ int  g_ps[NT];          // psg row (-1 = none)

// ---------------------------------------------------------------------------
// Exact coarse key: lo - log(-log u). Series path near u=1: winners have
// u ~ 1-3e-5 where __logf's ~1e-6 ABSOLUTE error would be catastrophic
// relative error on t = -log u. Abs key error bounded ~1.2e-4.
// ---------------------------------------------------------------------------
__device__ __forceinline__ float coarse_key(float lo, float u) {
    float w  = 1.0f - u;                 // exact for u > 0.5 (Sterbenz)
    float ts = fmaf(0.5f * w, w, w);     // w + w^2/2
    float tl = -__logf(u);
    float t  = (u > 0.99609375f) ? ts : tl;
    return lo - __logf(t);
}

__device__ __forceinline__ double precise_key(float lo, float u) {
    return (double)lo - log(-log((double)u));
}

__device__ __forceinline__ void ins2(float k, int j,
                                     float& v1, int& i1,
                                     float& v2, int& i2) {
    bool p = k > v1;
    float dv = p ? v1 : k;
    int   di = p ? i1 : j;
    if (p) { v1 = k; i1 = j; }
    if (dv > v2) { v2 = dv; i2 = di; }
}

__device__ __forceinline__ void top2_insert(float w, int j,
                                            float& v1, int& i1,
                                            float& v2, int& i2) {
    if (w > v1 || (w == v1 && j < i1)) {
        v2 = v1; i2 = i1; v1 = w; i1 = j;
    } else if (w > v2 || (w == v2 && j < i2)) {
        v2 = w; i2 = j;
    }
}

// ---------------------------------------------------------------------------
// K0: psg prep. One warp per batch, shuffle reductions only (~1.4us).
// ---------------------------------------------------------------------------
__global__ void __launch_bounds__(32)
psg_prep_kernel(const int* __restrict__ rwrt,
                const int* __restrict__ psg_in) {
    __shared__ int s_r[LL];
    __shared__ int s_p[LL];
    const int b    = blockIdx.x;
    const int lane = threadIdx.x;

    int cnt = 0;
#pragma unroll
    for (int k = 0; k < LL / 32; k++) {
        int l  = lane + 32 * k;
        int rv = rwrt[b * LL + l];
        s_r[l] = rv;
        s_p[l] = psg_in[b * LL + l];
        cnt += (rv == 1);
    }
    __syncwarp();
#pragma unroll
    for (int o = 16; o > 0; o >>= 1) cnt += __shfl_xor_sync(0xFFFFFFFFu, cnt, o);
    const int shift = cnt;

    int tr[LL / 32];
    int firstnz = LL;
#pragma unroll
    for (int k = 0; k < LL / 32; k++) {
        int l   = lane + 32 * k;
        int pos = ((l - shift) % LL + LL) % LL;
        int fm  = 1 - s_r[LL - 1 - pos];
        int psv = (pos == 0) ? 1 : s_p[pos - 1];
        int t   = fm * psv;
        tr[k] = t;
        if (t != 0) firstnz = min(firstnz, l);
    }
#pragma unroll
    for (int o = 16; o > 0; o >>= 1)
        firstnz = min(firstnz, __shfl_xor_sync(0xFFFFFFFFu, firstnz, o));

#pragma unroll
    for (int k = 0; k < LL / 32; k++) {
        int l = lane + 32 * k;
        g_ps[b * LL + l] = (l >= firstnz) ? tr[k] : -1;
    }
}

// ---------------------------------------------------------------------------
// K1: streaming scan — best-measured variant (R4/R5), untouched.
// Per-element independent bit-log UB filter + smem block top-2 tree.
// ---------------------------------------------------------------------------
__global__ void __launch_bounds__(NTH)
scan_kernel(const float* __restrict__ logits,
            const float* __restrict__ gu) {
    const int blk = blockIdx.x;
    const int t   = blk >> 2;
    const int c   = blk & 3;
    const int tid = threadIdx.x;

    const float4* lg = (const float4*)(logits + (size_t)t * VV) + c * CV4;
    const float4* gg = (const float4*)(gu     + (size_t)t * VV) + c * CV4;
    const int jbase = c * CV4 * 4;

    float v1 = -INFINITY, v2 = -INFINITY;
    int   i1 = 0,         i2 = 1;

    // seed: one exact float4 per lane, warp-wide 2nd-max -> thr
    {
        float4 a = __ldcs(lg + tid);
        float4 g = __ldcs(gg + tid);
        int base = jbase + 4 * tid;
        ins2(coarse_key(a.x, g.x), base + 0, v1, i1, v2, i2);
        ins2(coarse_key(a.y, g.y), base + 1, v1, i1, v2, i2);
        ins2(coarse_key(a.z, g.z), base + 2, v1, i1, v2, i2);
        ins2(coarse_key(a.w, g.w), base + 3, v1, i1, v2, i2);
    }
    float sa = v1, sb = v2;
#pragma unroll
    for (int off = 16; off > 0; off >>= 1) {
        float oa = __shfl_xor_sync(0xFFFFFFFFu, sa, off);
        float ob = __shfl_xor_sync(0xFFFFFFFFu, sb, off);
        float hi  = fmaxf(sa, oa);
        float lo2 = fmaxf(fminf(sa, oa), fmaxf(sb, ob));
        sa = hi; sb = lo2;
    }
    float thr = fmaxf(v2, sb);   // provable lower bound on global #2

    const float CB  = 88.029693f;       // 127 * ln2
    const float CC  = 8.2629582e-8f;    // ln2 / 2^23
    const float EPS = 1e-5f;            // I2F rounding margin

    for (int i = tid + NTH; i < CV4; i += NTH) {
        float4 a = __ldcs(lg + i);
        float4 g = __ldcs(gg + i);
        // one-sided: key <= lo - ln2*l2a(1-u)  since -log u >= 1-u, l2a <= log2
        float ub0 = fmaf(-CC, (float)__float_as_int(1.0f - g.x), a.x + CB + EPS);
        float ub1 = fmaf(-CC, (float)__float_as_int(1.0f - g.y), a.y + CB + EPS);
        float ub2 = fmaf(-CC, (float)__float_as_int(1.0f - g.z), a.z + CB + EPS);
        float ub3 = fmaf(-CC, (float)__float_as_int(1.0f - g.w), a.w + CB + EPS);
        if (ub0 > thr || ub1 > thr || ub2 > thr || ub3 > thr) {
            int base = jbase + 4 * i;
            ins2(coarse_key(a.x, g.x), base + 0, v1, i1, v2, i2);
            ins2(coarse_key(a.y, g.y), base + 1, v1, i1, v2, i2);
            ins2(coarse_key(a.z, g.z), base + 2, v1, i1, v2, i2);
            ins2(coarse_key(a.w, g.w), base + 3, v1, i1, v2, i2);
            thr = fmaxf(thr, v2);
        }
    }

    __shared__ float s_v1[NTH]; __shared__ int s_i1[NTH];
    __shared__ float s_v2[NTH]; __shared__ int s_i2[NTH];
    s_v1[tid] = v1; s_i1[tid] = i1;
    s_v2[tid] = v2; s_i2[tid] = i2;
    __syncthreads();
    for (int s = NTH / 2; s > 0; s >>= 1) {
        if (tid < s) {
            float w1 = s_v1[tid + s], w2 = s_v2[tid + s];
            int   j1 = s_i1[tid + s], j2 = s_i2[tid + s];
            float a1 = s_v1[tid],     a2 = s_v2[tid];
            int   c1 = s_i1[tid],     c2 = s_i2[tid];
            top2_insert(w1, j1, a1, c1, a2, c2);
            top2_insert(w2, j2, a1, c1, a2, c2);
            s_v1[tid] = a1; s_i1[tid] = c1;
            s_v2[tid] = a2; s_i2[tid] = c2;
        }
        __syncthreads();
    }
    if (tid == 0) {
        g_part[blk] = make_int4(__float_as_int(s_v1[0]), s_i1[0],
                                __float_as_int(s_v2[0]), s_i2[0]);
    }
}

// ---------------------------------------------------------------------------
// K2: per-token finish. grid=NT x 192 threads, ZERO barriers, no smem.
// Every thread redundantly merges the 4 partials (L1 broadcast of the same
// 64B) and decides; then gathers its own float4 of the output row.
// ---------------------------------------------------------------------------
__global__ void __launch_bounds__(ND4)
finish_kernel(const float* __restrict__ logits,
              const float* __restrict__ gu,
              const float* __restrict__ W,
              const int*   __restrict__ rwrt,
              float*       __restrict__ out) {
    const int t = blockIdx.x;
    const int d = threadIdx.x;           // 0..191

    float v1 = -INFINITY, v2 = -INFINITY;
    int   i1 = 0,         i2 = 1;
#pragma unroll
    for (int cc = 0; cc < CH; cc++) {
        int4 pr = g_part[t * CH + cc];   // same addr for all threads: L1 bcast
        top2_insert(__int_as_float(pr.x), pr.y, v1, i1, v2, i2);
        top2_insert(__int_as_float(pr.z), pr.w, v1, i1, v2, i2);
    }
    int win = i1;
    if (v1 - v2 < 0.02f) {
        // rare (~2% of tokens): fp64 re-decide; same result in all threads
        double k1 = precise_key(logits[(size_t)t * VV + i1],
                                gu[(size_t)t * VV + i1]);
        double k2 = precise_key(logits[(size_t)t * VV + i2],
                                gu[(size_t)t * VV + i2]);
        if (k2 > k1 || (k2 == k1 && i2 < i1)) win = i2;
    }

    const int am = (rwrt[t] != 0 && win < AVV) ? win : -1;
    const int ps = g_ps[t];

    const float4* W4 = (const float4*)W;
    float4 acc = make_float4(0.f, 0.f, 0.f, 0.f);
    if (am >= 0) acc = W4[(size_t)am * ND4 + d];
    if (ps >= 0) {
        float4 wv = W4[(size_t)ps * ND4 + d];
        acc.x += wv.x; acc.y += wv.y; acc.z += wv.z; acc.w += wv.w;
    }
    ((float4*)out)[(size_t)t * ND4 + d] = acc;
}

// ---------------------------------------------------------------------------
extern "C" void kernel_launch(void* const* d_in, const int* in_sizes, int n_in,
                              void* d_out, int out_size) {
    const float* logits = (const float*)d_in[0];
    const float* gu     = (const float*)d_in[1];
    const float* W      = (const float*)d_in[2];
    const int*   rwrt   = (const int*)d_in[3];
    const int*   psg    = (const int*)d_in[4];
    float* out = (float*)d_out;

    psg_prep_kernel<<<BB, 32>>>(rwrt, psg);
    scan_kernel<<<NT * CH, NTH>>>(logits, gu);
    finish_kernel<<<NT, ND4>>>(logits, gu, W, rwrt, out);
}

// round 10
// speedup vs baseline: 1.0365x; 1.0218x over previous
#include <cuda_runtime.h>
#include <math.h>

#define BB 4
#define LL 512
#define VV 32128
#define AVV 32000
#define DD 768
#define NT (BB*LL)
#define NV4 (VV/4)      // 8032
#define ND4 (DD/4)      // 192
#define NTH 256
#define CH 4            // chunks per token
#define CV4 (NV4/CH)    // 2008 float4 per chunk

// Scratch (device globals; no allocation allowed)
__device__ int4 g_part[NT * CH];   // per (token,chunk) top-2: {bits(v1),i1,bits(v2),i2}
__device__ int  g_ps[NT];          // psg row (-1 = none)

// ---------------------------------------------------------------------------
// Exact coarse key: lo - log(-log u). Series path near u=1: winners have
// u ~ 1-3e-5 where __logf's ~1e-6 ABSOLUTE error would be catastrophic
// relative error on t = -log u. Abs key error bounded ~1.2e-4.
// ---------------------------------------------------------------------------
__device__ __forceinline__ float coarse_key(float lo, float u) {
    float w  = 1.0f - u;                 // exact for u > 0.5 (Sterbenz)
    float ts = fmaf(0.5f * w, w, w);     // w + w^2/2
    float tl = -__logf(u);
    float t  = (u > 0.99609375f) ? ts : tl;
    return lo - __logf(t);
}

__device__ __forceinline__ double precise_key(float lo, float u) {
    return (double)lo - log(-log((double)u));
}

__device__ __forceinline__ void ins2(float k, int j,
                                     float& v1, int& i1,
                                     float& v2, int& i2) {
    bool p = k > v1;
    float dv = p ? v1 : k;
    int   di = p ? i1 : j;
    if (p) { v1 = k; i1 = j; }
    if (dv > v2) { v2 = dv; i2 = di; }
}

__device__ __forceinline__ void top2_insert(float w, int j,
                                            float& v1, int& i1,
                                            float& v2, int& i2) {
    if (w > v1 || (w == v1 && j < i1)) {
        v2 = v1; i2 = i1; v1 = w; i1 = j;
    } else if (w > v2 || (w == v2 && j < i2)) {
        v2 = w; i2 = j;
    }
}

// ---------------------------------------------------------------------------
// K1: scan + embedded psg blocks.
// grid = BB + NT*CH. blk < BB: psg-only block (warp 0), runs in wave 1,
// fully hidden under the streaming scan. blk >= BB: one (token,chunk) scan.
// ---------------------------------------------------------------------------
__global__ void __launch_bounds__(NTH)
scan_kernel(const float* __restrict__ logits,
            const float* __restrict__ gu,
            const int*   __restrict__ rwrt,
            const int*   __restrict__ psg_in) {
    const int tid = threadIdx.x;

    // ---------------- psg blocks (hidden in wave 1) ----------------
    if (blockIdx.x < BB) {
        __shared__ int s_r[LL];
        __shared__ int s_p[LL];
        const int b = blockIdx.x;
        if (tid >= 32) return;
        const int lane = tid;

        int cnt = 0;
#pragma unroll
        for (int k = 0; k < LL / 32; k++) {
            int l  = lane + 32 * k;
            int rv = rwrt[b * LL + l];
            s_r[l] = rv;
            s_p[l] = psg_in[b * LL + l];
            cnt += (rv == 1);
        }
        __syncwarp();
#pragma unroll
        for (int o = 16; o > 0; o >>= 1)
            cnt += __shfl_xor_sync(0xFFFFFFFFu, cnt, o);
        const int shift = cnt;

        int tr[LL / 32];
        int firstnz = LL;
#pragma unroll
        for (int k = 0; k < LL / 32; k++) {
            int l   = lane + 32 * k;
            int pos = ((l - shift) % LL + LL) % LL;
            int fm  = 1 - s_r[LL - 1 - pos];
            int psv = (pos == 0) ? 1 : s_p[pos - 1];
            int t   = fm * psv;
            tr[k] = t;
            if (t != 0) firstnz = min(firstnz, l);
        }
#pragma unroll
        for (int o = 16; o > 0; o >>= 1)
            firstnz = min(firstnz, __shfl_xor_sync(0xFFFFFFFFu, firstnz, o));
#pragma unroll
        for (int k = 0; k < LL / 32; k++) {
            int l = lane + 32 * k;
            g_ps[b * LL + l] = (l >= firstnz) ? tr[k] : -1;
        }
        return;
    }

    // ---------------- scan blocks ----------------
    const int blk = blockIdx.x - BB;
    const int t   = blk >> 2;
    const int c   = blk & 3;

    const float4* lg = (const float4*)(logits + (size_t)t * VV) + c * CV4;
    const float4* gg = (const float4*)(gu     + (size_t)t * VV) + c * CV4;
    const int jbase = c * CV4 * 4;

    float v1 = -INFINITY, v2 = -INFINITY;
    int   i1 = 0,         i2 = 1;

    // seed: one exact float4 per lane, warp-wide 2nd-max -> thr
    {
        float4 a = __ldcs(lg + tid);
        float4 g = __ldcs(gg + tid);
        int base = jbase + 4 * tid;
        ins2(coarse_key(a.x, g.x), base + 0, v1, i1, v2, i2);
        ins2(coarse_key(a.y, g.y), base + 1, v1, i1, v2, i2);
        ins2(coarse_key(a.z, g.z), base + 2, v1, i1, v2, i2);
        ins2(coarse_key(a.w, g.w), base + 3, v1, i1, v2, i2);
    }
    float sa = v1, sb = v2;
#pragma unroll
    for (int off = 16; off > 0; off >>= 1) {
        float oa = __shfl_xor_sync(0xFFFFFFFFu, sa, off);
        float ob = __shfl_xor_sync(0xFFFFFFFFu, sb, off);
        float hi  = fmaxf(sa, oa);
        float lo2 = fmaxf(fminf(sa, oa), fmaxf(sb, ob));
        sa = hi; sb = lo2;
    }

    // thr2 = (lower bound on global #2) - (CB + EPS), folded once.
    const float CC  = 8.2629582e-8f;    // ln2 / 2^23
    const float CBE = 88.029703f;       // 127*ln2 + 1e-5 margin
    float thr2 = fmaxf(v2, sb) - CBE;

    // main loop: per-element UBs (independent FFMA), 3-FMAX tree, 1 FSETP.
    // test: max_e(lo_e - CC*bits(1-u_e)) > thr2  <=>  any per-element UB hit.
#pragma unroll 2
    for (int i = tid + NTH; i < CV4; i += NTH) {
        float4 a = __ldcs(lg + i);
        float4 g = __ldcs(gg + i);
        float ub0 = fmaf(-CC, (float)__float_as_int(1.0f - g.x), a.x);
        float ub1 = fmaf(-CC, (float)__float_as_int(1.0f - g.y), a.y);
        float ub2 = fmaf(-CC, (float)__float_as_int(1.0f - g.z), a.z);
        float ub3 = fmaf(-CC, (float)__float_as_int(1.0f - g.w), a.w);
        float m = fmaxf(fmaxf(ub0, ub1), fmaxf(ub2, ub3));
        if (m > thr2) {
            int base = jbase + 4 * i;
            ins2(coarse_key(a.x, g.x), base + 0, v1, i1, v2, i2);
            ins2(coarse_key(a.y, g.y), base + 1, v1, i1, v2, i2);
            ins2(coarse_key(a.z, g.z), base + 2, v1, i1, v2, i2);
            ins2(coarse_key(a.w, g.w), base + 3, v1, i1, v2, i2);
            thr2 = fmaxf(thr2, v2 - CBE);
        }
    }

    // block top-2 reduction (index tie-break)
    __shared__ float s_v1[NTH]; __shared__ int s_i1[NTH];
    __shared__ float s_v2[NTH]; __shared__ int s_i2[NTH];
    s_v1[tid] = v1; s_i1[tid] = i1;
    s_v2[tid] = v2; s_i2[tid] = i2;
    __syncthreads();
    for (int s = NTH / 2; s > 0; s >>= 1) {
        if (tid < s) {
            float w1 = s_v1[tid + s], w2 = s_v2[tid + s];
            int   j1 = s_i1[tid + s], j2 = s_i2[tid + s];
            float a1 = s_v1[tid],     a2 = s_v2[tid];
            int   c1 = s_i1[tid],     c2 = s_i2[tid];
            top2_insert(w1, j1, a1, c1, a2, c2);
            top2_insert(w2, j2, a1, c1, a2, c2);
            s_v1[tid] = a1; s_i1[tid] = c1;
            s_v2[tid] = a2; s_i2[tid] = c2;
        }
        __syncthreads();
    }
    if (tid == 0) {
        g_part[blk] = make_int4(__float_as_int(s_v1[0]), s_i1[0],
                                __float_as_int(s_v2[0]), s_i2[0]);
    }
}

// ---------------------------------------------------------------------------
// K2: per-token finish. grid=NT x 192 threads, zero barriers, no smem.
// Every thread redundantly merges the 4 partials (L1 broadcast) + decides,
// then gathers its own float4 of the output row.
// ---------------------------------------------------------------------------
__global__ void __launch_bounds__(ND4)
finish_kernel(const float* __restrict__ logits,
              const float* __restrict__ gu,
              const float* __restrict__ W,
              const int*   __restrict__ rwrt,
              float*       __restrict__ out) {
    const int t = blockIdx.x;
    const int d = threadIdx.x;           // 0..191

    float v1 = -INFINITY, v2 = -INFINITY;
    int   i1 = 0,         i2 = 1;
#pragma unroll
    for (int cc = 0; cc < CH; cc++) {
        int4 pr = g_part[t * CH + cc];   // same addr for all threads: L1 bcast
        top2_insert(__int_as_float(pr.x), pr.y, v1, i1, v2, i2);
        top2_insert(__int_as_float(pr.z), pr.w, v1, i1, v2, i2);
    }
    int win = i1;
    if (v1 - v2 < 0.02f) {
        // rare (~2% of tokens): fp64 re-decide; same result in all threads
        double k1 = precise_key(logits[(size_t)t * VV + i1],
                                gu[(size_t)t * VV + i1]);
        double k2 = precise_key(logits[(size_t)t * VV + i2],
                                gu[(size_t)t * VV + i2]);
        if (k2 > k1 || (k2 == k1 && i2 < i1)) win = i2;
    }

    const int am = (rwrt[t] != 0 && win < AVV) ? win : -1;
    const int ps = g_ps[t];

    const float4* W4 = (const float4*)W;
    float4 acc = make_float4(0.f, 0.f, 0.f, 0.f);
    if (am >= 0) acc = W4[(size_t)am * ND4 + d];
    if (ps >= 0) {
        float4 wv = W4[(size_t)ps * ND4 + d];
        acc.x += wv.x; acc.y += wv.y; acc.z += wv.z; acc.w += wv.w;
    }
    ((float4*)out)[(size_t)t * ND4 + d] = acc;
}

// ---------------------------------------------------------------------------
extern "C" void kernel_launch(void* const* d_in, const int* in_sizes, int n_in,
                              void* d_out, int out_size) {
    const float* logits = (const float*)d_in[0];
    const float* gu     = (const float*)d_in[1];
    const float* W      = (const float*)d_in[2];
    const int*   rwrt   = (const int*)d_in[3];
    const int*   psg    = (const int*)d_in[4];
    float* out = (float*)d_out;

    scan_kernel<<<BB + NT * CH, NTH>>>(logits, gu, rwrt, psg);
    finish_kernel<<<NT, ND4>>>(logits, gu, W, rwrt, out);
}

// round 11
// speedup vs baseline: 1.1272x; 1.0875x over previous
#include <cuda_runtime.h>
#include <math.h>

#define BB 4
#define LL 512
#define VV 32128
#define AVV 32000
#define DD 768
#define NT (BB*LL)
#define NV4 (VV/4)      // 8032
#define ND4 (DD/4)      // 192
#define NTH 256
#define CH 4            // chunks per token
#define CV4 (NV4/CH)    // 2008 float4 per chunk

// Scratch (device globals; no allocation allowed)
__device__ int4 g_part[NT * CH];   // per (token,chunk) top-2: {bits(v1),i1,bits(v2),i2}
__device__ int  g_ps[NT];          // psg row (-1 = none)

// ---------------------------------------------------------------------------
// Exact coarse key: lo - log(-log u). Series path near u=1: winners have
// u ~ 1-3e-5 where __logf's ~1e-6 ABSOLUTE error would be catastrophic
// relative error on t = -log u. Abs key error bounded ~1.2e-4.
// ---------------------------------------------------------------------------
__device__ __forceinline__ float coarse_key(float lo, float u) {
    float w  = 1.0f - u;                 // exact for u > 0.5 (Sterbenz)
    float ts = fmaf(0.5f * w, w, w);     // w + w^2/2
    float tl = -__logf(u);
    float t  = (u > 0.99609375f) ? ts : tl;
    return lo - __logf(t);
}

__device__ __forceinline__ double precise_key(float lo, float u) {
    return (double)lo - log(-log((double)u));
}

__device__ __forceinline__ void ins2(float k, int j,
                                     float& v1, int& i1,
                                     float& v2, int& i2) {
    bool p = k > v1;
    float dv = p ? v1 : k;
    int   di = p ? i1 : j;
    if (p) { v1 = k; i1 = j; }
    if (dv > v2) { v2 = dv; i2 = di; }
}

__device__ __forceinline__ void top2_insert(float w, int j,
                                            float& v1, int& i1,
                                            float& v2, int& i2) {
    if (w > v1 || (w == v1 && j < i1)) {
        v2 = v1; i2 = i1; v1 = w; i1 = j;
    } else if (w > v2 || (w == v2 && j < i2)) {
        v2 = w; i2 = j;
    }
}

// ---------------------------------------------------------------------------
// K1: scan + embedded psg blocks (identical to R10 — tied-best scan).
// grid = BB + NT*CH. blk < BB: psg-only block (hidden in wave 1).
// ---------------------------------------------------------------------------
__global__ void __launch_bounds__(NTH)
scan_kernel(const float* __restrict__ logits,
            const float* __restrict__ gu,
            const int*   __restrict__ rwrt,
            const int*   __restrict__ psg_in) {
    const int tid = threadIdx.x;

    // ---------------- psg blocks (hidden in wave 1) ----------------
    if (blockIdx.x < BB) {
        __shared__ int s_r[LL];
        __shared__ int s_p[LL];
        const int b = blockIdx.x;
        if (tid >= 32) return;
        const int lane = tid;

        int cnt = 0;
#pragma unroll
        for (int k = 0; k < LL / 32; k++) {
            int l  = lane + 32 * k;
            int rv = rwrt[b * LL + l];
            s_r[l] = rv;
            s_p[l] = psg_in[b * LL + l];
            cnt += (rv == 1);
        }
        __syncwarp();
#pragma unroll
        for (int o = 16; o > 0; o >>= 1)
            cnt += __shfl_xor_sync(0xFFFFFFFFu, cnt, o);
        const int shift = cnt;

        int tr[LL / 32];
        int firstnz = LL;
#pragma unroll
        for (int k = 0; k < LL / 32; k++) {
            int l   = lane + 32 * k;
            int pos = ((l - shift) % LL + LL) % LL;
            int fm  = 1 - s_r[LL - 1 - pos];
            int psv = (pos == 0) ? 1 : s_p[pos - 1];
            int t   = fm * psv;
            tr[k] = t;
            if (t != 0) firstnz = min(firstnz, l);
        }
#pragma unroll
        for (int o = 16; o > 0; o >>= 1)
            firstnz = min(firstnz, __shfl_xor_sync(0xFFFFFFFFu, firstnz, o));
#pragma unroll
        for (int k = 0; k < LL / 32; k++) {
            int l = lane + 32 * k;
            g_ps[b * LL + l] = (l >= firstnz) ? tr[k] : -1;
        }
        return;
    }

    // ---------------- scan blocks ----------------
    const int blk = blockIdx.x - BB;
    const int t   = blk >> 2;
    const int c   = blk & 3;

    const float4* lg = (const float4*)(logits + (size_t)t * VV) + c * CV4;
    const float4* gg = (const float4*)(gu     + (size_t)t * VV) + c * CV4;
    const int jbase = c * CV4 * 4;

    float v1 = -INFINITY, v2 = -INFINITY;
    int   i1 = 0,         i2 = 1;

    // seed: one exact float4 per lane, warp-wide 2nd-max -> thr
    {
        float4 a = __ldcs(lg + tid);
        float4 g = __ldcs(gg + tid);
        int base = jbase + 4 * tid;
        ins2(coarse_key(a.x, g.x), base + 0, v1, i1, v2, i2);
        ins2(coarse_key(a.y, g.y), base + 1, v1, i1, v2, i2);
        ins2(coarse_key(a.z, g.z), base + 2, v1, i1, v2, i2);
        ins2(coarse_key(a.w, g.w), base + 3, v1, i1, v2, i2);
    }
    float sa = v1, sb = v2;
#pragma unroll
    for (int off = 16; off > 0; off >>= 1) {
        float oa = __shfl_xor_sync(0xFFFFFFFFu, sa, off);
        float ob = __shfl_xor_sync(0xFFFFFFFFu, sb, off);
        float hi  = fmaxf(sa, oa);
        float lo2 = fmaxf(fminf(sa, oa), fmaxf(sb, ob));
        sa = hi; sb = lo2;
    }

    // thr2 = (lower bound on global #2) - (CB + EPS), folded once.
    const float CC  = 8.2629582e-8f;    // ln2 / 2^23
    const float CBE = 88.029703f;       // 127*ln2 + 1e-5 margin
    float thr2 = fmaxf(v2, sb) - CBE;

    // main loop: per-element UBs (independent FFMA), 3-FMAX tree, 1 FSETP.
#pragma unroll 2
    for (int i = tid + NTH; i < CV4; i += NTH) {
        float4 a = __ldcs(lg + i);
        float4 g = __ldcs(gg + i);
        float ub0 = fmaf(-CC, (float)__float_as_int(1.0f - g.x), a.x);
        float ub1 = fmaf(-CC, (float)__float_as_int(1.0f - g.y), a.y);
        float ub2 = fmaf(-CC, (float)__float_as_int(1.0f - g.z), a.z);
        float ub3 = fmaf(-CC, (float)__float_as_int(1.0f - g.w), a.w);
        float m = fmaxf(fmaxf(ub0, ub1), fmaxf(ub2, ub3));
        if (m > thr2) {
            int base = jbase + 4 * i;
            ins2(coarse_key(a.x, g.x), base + 0, v1, i1, v2, i2);
            ins2(coarse_key(a.y, g.y), base + 1, v1, i1, v2, i2);
            ins2(coarse_key(a.z, g.z), base + 2, v1, i1, v2, i2);
            ins2(coarse_key(a.w, g.w), base + 3, v1, i1, v2, i2);
            thr2 = fmaxf(thr2, v2 - CBE);
        }
    }

    // block top-2 reduction (index tie-break)
    __shared__ float s_v1[NTH]; __shared__ int s_i1[NTH];
    __shared__ float s_v2[NTH]; __shared__ int s_i2[NTH];
    s_v1[tid] = v1; s_i1[tid] = i1;
    s_v2[tid] = v2; s_i2[tid] = i2;
    __syncthreads();
    for (int s = NTH / 2; s > 0; s >>= 1) {
        if (tid < s) {
            float w1 = s_v1[tid + s], w2 = s_v2[tid + s];
            int   j1 = s_i1[tid + s], j2 = s_i2[tid + s];
            float a1 = s_v1[tid],     a2 = s_v2[tid];
            int   c1 = s_i1[tid],     c2 = s_i2[tid];
            top2_insert(w1, j1, a1, c1, a2, c2);
            top2_insert(w2, j2, a1, c1, a2, c2);
            s_v1[tid] = a1; s_i1[tid] = c1;
            s_v2[tid] = a2; s_i2[tid] = c2;
        }
        __syncthreads();
    }
    if (tid == 0) {
        g_part[blk] = make_int4(__float_as_int(s_v1[0]), s_i1[0],
                                __float_as_int(s_v2[0]), s_i2[0]);
    }
}

// ---------------------------------------------------------------------------
// K2: per-token finish. grid=NT x 192.  Warp 0 decides (lanes 0-3 load the
// 4 partials in parallel, shuffle-merge, t0 resolves near-tie), ONE barrier,
// then all threads gather.  fp64 path now executes in 1 thread of ~0.4% of
// blocks instead of 192 threads of 2%.
// ---------------------------------------------------------------------------
__global__ void __launch_bounds__(ND4)
finish_kernel(const float* __restrict__ logits,
              const float* __restrict__ gu,
              const float* __restrict__ W,
              const int*   __restrict__ rwrt,
              float*       __restrict__ out) {
    const int t = blockIdx.x;
    const int d = threadIdx.x;           // 0..191

    __shared__ int s_res[2];             // [0]=am, [1]=ps

    if (d < 32) {
        // lanes 0-3 fetch the 4 partials concurrently (MLP=4, one latency)
        float v1 = -INFINITY, v2 = -INFINITY;
        int   i1 = 0,         i2 = 1;
        if (d < CH) {
            int4 pr = g_part[t * CH + d];
            v1 = __int_as_float(pr.x); i1 = pr.y;
            v2 = __int_as_float(pr.z); i2 = pr.w;
        }
        // shuffle-merge across lanes 0-7 (only 0-3 carry data)
#pragma unroll
        for (int off = 4; off > 0; off >>= 1) {
            float w1 = __shfl_xor_sync(0xFFFFFFFFu, v1, off);
            int   j1 = __shfl_xor_sync(0xFFFFFFFFu, i1, off);
            float w2 = __shfl_xor_sync(0xFFFFFFFFu, v2, off);
            int   j2 = __shfl_xor_sync(0xFFFFFFFFu, i2, off);
            top2_insert(w1, j1, v1, i1, v2, i2);
            top2_insert(w2, j2, v1, i1, v2, i2);
        }
        if (d == 0) {
            int win = i1;
            if (v1 - v2 < 4e-3f) {
                // near-tie (rate ~0.4%): fp64 re-decide.  Coarse pair error
                // <= 2.4e-4, 16x margin below threshold.
                double k1 = precise_key(logits[(size_t)t * VV + i1],
                                        gu[(size_t)t * VV + i1]);
                double k2 = precise_key(logits[(size_t)t * VV + i2],
                                        gu[(size_t)t * VV + i2]);
                if (k2 > k1 || (k2 == k1 && i2 < i1)) win = i2;
            }
            s_res[0] = (rwrt[t] != 0 && win < AVV) ? win : -1;
            s_res[1] = g_ps[t];
        }
    }
    __syncthreads();

    const int am = s_res[0];
    const int ps = s_res[1];

    const float4* W4 = (const float4*)W;
    float4 acc = make_float4(0.f, 0.f, 0.f, 0.f);
    if (am >= 0) acc = W4[(size_t)am * ND4 + d];
    if (ps >= 0) {
        float4 wv = W4[(size_t)ps * ND4 + d];
        acc.x += wv.x; acc.y += wv.y; acc.z += wv.z; acc.w += wv.w;
    }
    ((float4*)out)[(size_t)t * ND4 + d] = acc;
}

// ---------------------------------------------------------------------------
extern "C" void kernel_launch(void* const* d_in, const int* in_sizes, int n_in,
                              void* d_out, int out_size) {
    const float* logits = (const float*)d_in[0];
    const float* gu     = (const float*)d_in[1];
    const float* W      = (const float*)d_in[2];
    const int*   rwrt   = (const int*)d_in[3];
    const int*   psg    = (const int*)d_in[4];
    float* out = (float*)d_out;

    scan_kernel<<<BB + NT * CH, NTH>>>(logits, gu, rwrt, psg);
    finish_kernel<<<NT, ND4>>>(logits, gu, W, rwrt, out);
}